// round 5
// baseline (speedup 1.0000x reference)
#include <cuda_runtime.h>

// Haar DWT2, single level.
// x: [8, 64, 512, 512] f32  ->  out: 4 subbands (ll, lh, hl, hh) concatenated,
// each [8, 64, 256, 256] f32.
//
// Streaming kernel, HBM-bound. Each thread consumes a 2x16 input patch
// (8 front-batched float4 loads = 128 B) and produces 2 float4 per subband
// (8 float4 stores = 128 B). One warp covers exactly one full input row-pair.
// Evict-first cache hints on both paths (data touched exactly once).

#define W_IN       512
#define SUBBAND_N  33554432u  // 512 * 256 * 256

__global__ void __launch_bounds__(256)
haar_dwt2_kernel(const float* __restrict__ x, float* __restrict__ out)
{
    unsigned tid = blockIdx.x * blockDim.x + threadIdx.x;

    // tid = ((bc * 256) + i) * 32 + q
    unsigned q  = tid & 31u;          // 8-output-col group (j0 = 8*q)
    unsigned i  = (tid >> 5) & 255u;  // output row
    unsigned bc = tid >> 13;          // fused batch*channel (0..511)

    // Input base element: ((bc*512 + 2*i) * 512 + 16*q)
    unsigned in_base = ((bc << 9) + (i << 1)) * (unsigned)W_IN + (q << 4);

    const float4* p0 = (const float4*)(x + in_base);          // row 2i
    const float4* p1 = (const float4*)(x + in_base + W_IN);   // row 2i+1

    // 8 independent front-batched loads (MLP_p1 = 8), streaming policy
    float4 r00 = __ldcs(p0 + 0);
    float4 r01 = __ldcs(p0 + 1);
    float4 r02 = __ldcs(p0 + 2);
    float4 r03 = __ldcs(p0 + 3);
    float4 r10 = __ldcs(p1 + 0);
    float4 r11 = __ldcs(p1 + 1);
    float4 r12 = __ldcs(p1 + 2);
    float4 r13 = __ldcs(p1 + 3);

    const float s = 0.5f;

    // Output element offset within a subband: ((bc*256 + i) * 256 + 8*q)
    unsigned out_off = (((bc << 8) + i) << 8) + (q << 3);

    float4* oll = (float4*)(out + out_off);
    float4* olh = (float4*)(out + SUBBAND_N      + out_off);
    float4* ohl = (float4*)(out + 2u * SUBBAND_N + out_off);
    float4* ohh = (float4*)(out + 3u * SUBBAND_N + out_off);

    // Process two 4-output-column halves
    {
        // Half 0: input float4s r00, r01 (row 2i) and r10, r11 (row 2i+1)
        float4 a = make_float4(r00.x, r00.z, r01.x, r01.z);
        float4 b = make_float4(r00.y, r00.w, r01.y, r01.w);
        float4 c = make_float4(r10.x, r10.z, r11.x, r11.z);
        float4 d = make_float4(r10.y, r10.w, r11.y, r11.w);

        float4 ll = make_float4((a.x + b.x + c.x + d.x) * s,
                                (a.y + b.y + c.y + d.y) * s,
                                (a.z + b.z + c.z + d.z) * s,
                                (a.w + b.w + c.w + d.w) * s);
        float4 lh = make_float4((a.x + b.x - c.x - d.x) * s,
                                (a.y + b.y - c.y - d.y) * s,
                                (a.z + b.z - c.z - d.z) * s,
                                (a.w + b.w - c.w - d.w) * s);
        float4 hl = make_float4((a.x - b.x + c.x - d.x) * s,
                                (a.y - b.y + c.y - d.y) * s,
                                (a.z - b.z + c.z - d.z) * s,
                                (a.w - b.w + c.w - d.w) * s);
        float4 hh = make_float4((a.x - b.x - c.x + d.x) * s,
                                (a.y - b.y - c.y + d.y) * s,
                                (a.z - b.z - c.z + d.z) * s,
                                (a.w - b.w - c.w + d.w) * s);

        __stcs(oll + 0, ll);
        __stcs(olh + 0, lh);
        __stcs(ohl + 0, hl);
        __stcs(ohh + 0, hh);
    }
    {
        // Half 1: input float4s r02, r03 (row 2i) and r12, r13 (row 2i+1)
        float4 a = make_float4(r02.x, r02.z, r03.x, r03.z);
        float4 b = make_float4(r02.y, r02.w, r03.y, r03.w);
        float4 c = make_float4(r12.x, r12.z, r13.x, r13.z);
        float4 d = make_float4(r12.y, r12.w, r13.y, r13.w);

        float4 ll = make_float4((a.x + b.x + c.x + d.x) * s,
                                (a.y + b.y + c.y + d.y) * s,
                                (a.z + b.z + c.z + d.z) * s,
                                (a.w + b.w + c.w + d.w) * s);
        float4 lh = make_float4((a.x + b.x - c.x - d.x) * s,
                                (a.y + b.y - c.y - d.y) * s,
                                (a.z + b.z - c.z - d.z) * s,
                                (a.w + b.w - c.w - d.w) * s);
        float4 hl = make_float4((a.x - b.x + c.x - d.x) * s,
                                (a.y - b.y + c.y - d.y) * s,
                                (a.z - b.z + c.z - d.z) * s,
                                (a.w - b.w + c.w - d.w) * s);
        float4 hh = make_float4((a.x - b.x - c.x + d.x) * s,
                                (a.y - b.y - c.y + d.y) * s,
                                (a.z - b.z - c.z + d.z) * s,
                                (a.w - b.w - c.w + d.w) * s);

        __stcs(oll + 1, ll);
        __stcs(olh + 1, lh);
        __stcs(ohl + 1, hl);
        __stcs(ohh + 1, hh);
    }
}

extern "C" void kernel_launch(void* const* d_in, const int* in_sizes, int n_in,
                              void* d_out, int out_size)
{
    const float* x = (const float*)d_in[0];
    float* out = (float*)d_out;

    // Total threads = 512 * 256 * 32 = 4,194,304; 256 threads/block
    dim3 grid(4194304u / 256u);
    dim3 block(256);
    haar_dwt2_kernel<<<grid, block>>>(x, out);
}

// round 6
// speedup vs baseline: 1.2337x; 1.2337x over previous
#include <cuda_runtime.h>

// Haar DWT2, single level.
// x: [8, 64, 512, 512] f32  ->  out: 4 subbands (ll, lh, hl, hh) concatenated,
// each [8, 64, 256, 256] f32.
//
// R2 structure (best: 157.7us, DRAM=86%): each thread reads a 2x8 input patch
// (4 front-batched float4 loads) and writes one float4 per subband.
// Single isolated delta vs R2: evict-first (.cs) hints on the 4 stores only.

#define W_IN       512
#define SUBBAND_N  33554432u  // 512 * 256 * 256

__global__ void __launch_bounds__(256, 8)
haar_dwt2_kernel(const float* __restrict__ x, float* __restrict__ out)
{
    unsigned tid = blockIdx.x * blockDim.x + threadIdx.x;

    // tid = ((bc * 256) + i) * 64 + q   (all powers of two -> shifts)
    unsigned q  = tid & 63u;          // quad index along output width (j0 = 4*q)
    unsigned i  = (tid >> 6) & 255u;  // output row
    unsigned bc = tid >> 14;          // fused batch*channel index (0..511)

    // Input base: element ((bc*512 + 2*i) * 512 + 8*q)
    unsigned in_base = ((bc << 9) + (i << 1)) * (unsigned)W_IN + (q << 3);

    const float4* p0 = (const float4*)(x + in_base);            // row 2i
    const float4* p1 = (const float4*)(x + in_base + W_IN);     // row 2i+1

    // Front-batched independent loads (MLP = 4), default cache policy
    float4 r0a = p0[0];
    float4 r0b = p0[1];
    float4 r1a = p1[0];
    float4 r1b = p1[1];

    // De-interleave columns: a = even cols (row 2i), b = odd cols (row 2i),
    //                        c = even cols (row 2i+1), d = odd cols (row 2i+1)
    float4 a = make_float4(r0a.x, r0a.z, r0b.x, r0b.z);
    float4 b = make_float4(r0a.y, r0a.w, r0b.y, r0b.w);
    float4 c = make_float4(r1a.x, r1a.z, r1b.x, r1b.z);
    float4 d = make_float4(r1a.y, r1a.w, r1b.y, r1b.w);

    const float s = 0.5f;

    float4 ll, lh, hl, hh;
    ll.x = (a.x + b.x + c.x + d.x) * s;
    ll.y = (a.y + b.y + c.y + d.y) * s;
    ll.z = (a.z + b.z + c.z + d.z) * s;
    ll.w = (a.w + b.w + c.w + d.w) * s;

    lh.x = (a.x + b.x - c.x - d.x) * s;
    lh.y = (a.y + b.y - c.y - d.y) * s;
    lh.z = (a.z + b.z - c.z - d.z) * s;
    lh.w = (a.w + b.w - c.w - d.w) * s;

    hl.x = (a.x - b.x + c.x - d.x) * s;
    hl.y = (a.y - b.y + c.y - d.y) * s;
    hl.z = (a.z - b.z + c.z - d.z) * s;
    hl.w = (a.w - b.w + c.w - d.w) * s;

    hh.x = (a.x - b.x - c.x + d.x) * s;
    hh.y = (a.y - b.y - c.y + d.y) * s;
    hh.z = (a.z - b.z - c.z + d.z) * s;
    hh.w = (a.w - b.w - c.w + d.w) * s;

    // Output element offset within a subband: ((bc*256 + i) * 256 + 4*q)
    unsigned out_off = (((bc << 8) + i) << 8) + (q << 2);

    __stcs((float4*)(out + out_off), ll);
    __stcs((float4*)(out + SUBBAND_N      + out_off), lh);
    __stcs((float4*)(out + 2u * SUBBAND_N + out_off), hl);
    __stcs((float4*)(out + 3u * SUBBAND_N + out_off), hh);
}

extern "C" void kernel_launch(void* const* d_in, const int* in_sizes, int n_in,
                              void* d_out, int out_size)
{
    const float* x = (const float*)d_in[0];
    float* out = (float*)d_out;

    // Total quads = 512 * 256 * 64 = 8,388,608 threads; 256 threads/block
    dim3 grid(8388608u / 256u);
    dim3 block(256);
    haar_dwt2_kernel<<<grid, block>>>(x, out);
}